// round 1
// baseline (speedup 1.0000x reference)
#include <cuda_runtime.h>

#define N_NODES 100000
#define N_EDGES 1000000
#define N_GRAPHS 2048
#define SCAN_BS 512
#define SCAN_NB ((N_NODES + SCAN_BS - 1) / SCAN_BS)

typedef unsigned long long u64;

// ---------------- device scratch (no allocs allowed) ----------------
__device__ float g_hA[N_NODES * 64];
__device__ float g_hB[N_NODES * 64];
__device__ float g_mean[N_NODES * 64];
__device__ int   g_deg[N_NODES];
__device__ int   g_rowptr[N_NODES + 1];
__device__ int   g_cursor[N_NODES];
__device__ int   g_colsrc[N_EDGES];
__device__ int   g_bsum[SCAN_NB];

// ---------------- f32x2 packed-FMA helpers (Blackwell FFMA2) ----------------
__device__ __forceinline__ u64 pk2(float x) {
    u64 r; asm("mov.b64 %0, {%1, %1};" : "=l"(r) : "f"(x)); return r;
}
__device__ __forceinline__ void fma2(u64 &d, u64 a, u64 b) {
    asm("fma.rn.f32x2 %0, %1, %2, %0;" : "+l"(d) : "l"(a), "l"(b));
}
__device__ __forceinline__ float2 up2(u64 v) {
    float lo, hi; asm("mov.b64 {%0, %1}, %2;" : "=f"(lo), "=f"(hi) : "l"(v));
    float2 f; f.x = lo; f.y = hi; return f;
}

// ---------------- CSR build ----------------
__global__ void k_zero_deg() {
    int i = blockIdx.x * blockDim.x + threadIdx.x;
    if (i < N_NODES) g_deg[i] = 0;
}

__global__ void k_hist(const int* __restrict__ dst) {
    int e = blockIdx.x * blockDim.x + threadIdx.x;
    if (e < N_EDGES) atomicAdd(&g_deg[dst[e]], 1);
}

__global__ void k_scan1() {
    __shared__ int s[SCAN_BS];
    int i = blockIdx.x * SCAN_BS + threadIdx.x;
    s[threadIdx.x] = (i < N_NODES) ? g_deg[i] : 0;
    __syncthreads();
    for (int off = SCAN_BS / 2; off; off >>= 1) {
        if (threadIdx.x < off) s[threadIdx.x] += s[threadIdx.x + off];
        __syncthreads();
    }
    if (threadIdx.x == 0) g_bsum[blockIdx.x] = s[0];
}

__global__ void k_scan2() {
    int run = 0;
    for (int b = 0; b < SCAN_NB; b++) { int t = g_bsum[b]; g_bsum[b] = run; run += t; }
}

__global__ void k_scan3() {
    __shared__ int s[SCAN_BS];
    int t = threadIdx.x;
    int i = blockIdx.x * SCAN_BS + t;
    int v = (i < N_NODES) ? g_deg[i] : 0;
    s[t] = v;
    __syncthreads();
    for (int off = 1; off < SCAN_BS; off <<= 1) {
        int x = (t >= off) ? s[t - off] : 0;
        __syncthreads();
        s[t] += x;
        __syncthreads();
    }
    int excl = s[t] - v + g_bsum[blockIdx.x];
    if (i < N_NODES) {
        g_rowptr[i] = excl;
        g_cursor[i] = excl;
        if (i == N_NODES - 1) g_rowptr[N_NODES] = excl + v;
    }
}

__global__ void k_fill(const int* __restrict__ src, const int* __restrict__ dst) {
    int e = blockIdx.x * blockDim.x + threadIdx.x;
    if (e >= N_EDGES) return;
    int p = atomicAdd(&g_cursor[dst[e]], 1);
    g_colsrc[p] = src[e];
}

// ---------------- embedding gather ----------------
__global__ void k_embed(const int* __restrict__ x, const float* __restrict__ emb,
                        float* __restrict__ out) {
    int i = blockIdx.x * blockDim.x + threadIdx.x;
    if (i >= N_NODES * 16) return;
    int n = i >> 4, q = i & 15;
    ((float4*)out)[i] = ((const float4*)emb)[(__ldg(x + n) << 4) + q];
}

// ---------------- neighbor mean aggregation (warp per node) ----------------
__global__ void k_agg(const float* __restrict__ h, float* __restrict__ mean) {
    int w = (blockIdx.x * blockDim.x + threadIdx.x) >> 5;
    if (w >= N_NODES) return;
    int lane = threadIdx.x & 31;
    int s = g_rowptr[w], e = g_rowptr[w + 1];
    float ax = 0.f, ay = 0.f;
    int i = s;
    for (; i + 4 <= e; i += 4) {
        int u0 = g_colsrc[i], u1 = g_colsrc[i + 1], u2 = g_colsrc[i + 2], u3 = g_colsrc[i + 3];
        float2 v0 = *(const float2*)(h + u0 * 64 + lane * 2);
        float2 v1 = *(const float2*)(h + u1 * 64 + lane * 2);
        float2 v2 = *(const float2*)(h + u2 * 64 + lane * 2);
        float2 v3 = *(const float2*)(h + u3 * 64 + lane * 2);
        ax += v0.x + v1.x + v2.x + v3.x;
        ay += v0.y + v1.y + v2.y + v3.y;
    }
    for (; i < e; ++i) {
        int u = g_colsrc[i];
        float2 v = *(const float2*)(h + u * 64 + lane * 2);
        ax += v.x; ay += v.y;
    }
    float inv = 1.f / (float)max(e - s, 1);
    float2 o; o.x = ax * inv; o.y = ay * inv;
    *(float2*)(mean + w * 64 + lane * 2) = o;
}

// ---------------- fused dual GEMM + bias + relu ----------------
// out[n,:] = relu(mean[n,:] @ Wl + h[n,:] @ Wr + b), one thread per node,
// 32 packed f32x2 accumulators, weights staged in shared as LDS.128 broadcasts.
__global__ void __launch_bounds__(256)
k_mm(const float* __restrict__ Am, const float* __restrict__ Ah,
     const float* __restrict__ Wl, const float* __restrict__ Wr,
     const float* __restrict__ bias, float* __restrict__ out) {
    __shared__ ulonglong2 sWl[64 * 16];
    __shared__ ulonglong2 sWr[64 * 16];
    __shared__ u64 sB[32];
    int t = threadIdx.x;
    const ulonglong2* gWl = (const ulonglong2*)Wl;
    const ulonglong2* gWr = (const ulonglong2*)Wr;
    for (int i = t; i < 1024; i += 256) { sWl[i] = gWl[i]; sWr[i] = gWr[i]; }
    if (t < 32) sB[t] = ((const u64*)bias)[t];
    __syncthreads();
    int n = blockIdx.x * 256 + t;
    if (n >= N_NODES) return;

    u64 acc[32];
#pragma unroll
    for (int j = 0; j < 32; j++) acc[j] = sB[j];

    const float* am = Am + n * 64;
    const float* ah = Ah + n * 64;
#pragma unroll 4
    for (int k = 0; k < 64; k++) {
        u64 a2 = pk2(__ldg(am + k));
        u64 c2 = pk2(__ldg(ah + k));
        const ulonglong2* wl = sWl + k * 16;
        const ulonglong2* wr = sWr + k * 16;
#pragma unroll
        for (int j = 0; j < 16; j++) {
            ulonglong2 l = wl[j], r = wr[j];
            fma2(acc[2 * j],     a2, l.x);
            fma2(acc[2 * j + 1], a2, l.y);
            fma2(acc[2 * j],     c2, r.x);
            fma2(acc[2 * j + 1], c2, r.y);
        }
    }

    float4* o4 = (float4*)(out + n * 64);
#pragma unroll
    for (int j = 0; j < 16; j++) {
        float2 p = up2(acc[2 * j]);
        float2 q = up2(acc[2 * j + 1]);
        float4 o;
        o.x = fmaxf(p.x, 0.f); o.y = fmaxf(p.y, 0.f);
        o.z = fmaxf(q.x, 0.f); o.w = fmaxf(q.y, 0.f);
        o4[j] = o;
    }
}

// ---------------- fused mean-pool + output head (warp per graph) ----------------
__global__ void k_pool(const float* __restrict__ h, const int* __restrict__ batch,
                       const float* __restrict__ Wout, const float* __restrict__ bout,
                       float* __restrict__ out) {
    int g = (blockIdx.x * blockDim.x + threadIdx.x) >> 5;
    if (g >= N_GRAPHS) return;
    int lane = threadIdx.x & 31;
    int s, e;
    { int lo = 0, hi = N_NODES;
      while (lo < hi) { int m = (lo + hi) >> 1; if (__ldg(batch + m) < g) lo = m + 1; else hi = m; }
      s = lo; }
    { int lo = s, hi = N_NODES;
      while (lo < hi) { int m = (lo + hi) >> 1; if (__ldg(batch + m) < g + 1) lo = m + 1; else hi = m; }
      e = lo; }
    float a0 = 0.f, a1 = 0.f;
    for (int n = s; n < e; ++n) {
        a0 += h[n * 64 + lane];
        a1 += h[n * 64 + lane + 32];
    }
    float inv = 1.f / (float)max(e - s, 1);
    a0 *= inv; a1 *= inv;
    float p0 = a0 * __ldg(Wout + lane * 2 + 0) + a1 * __ldg(Wout + (lane + 32) * 2 + 0);
    float p1 = a0 * __ldg(Wout + lane * 2 + 1) + a1 * __ldg(Wout + (lane + 32) * 2 + 1);
#pragma unroll
    for (int off = 16; off; off >>= 1) {
        p0 += __shfl_xor_sync(0xffffffffu, p0, off);
        p1 += __shfl_xor_sync(0xffffffffu, p1, off);
    }
    if (lane == 0) {
        out[g * 2 + 0] = p0 + __ldg(bout + 0);
        out[g * 2 + 1] = p1 + __ldg(bout + 1);
    }
}

// ---------------- launch ----------------
extern "C" void kernel_launch(void* const* d_in, const int* in_sizes, int n_in,
                              void* d_out, int out_size) {
    const int*   x     = (const int*)d_in[0];
    const int*   ei    = (const int*)d_in[1];
    const int*   batch = (const int*)d_in[2];
    const float* emb   = (const float*)d_in[3];
    const float* W1l   = (const float*)d_in[4];
    const float* b1    = (const float*)d_in[5];
    const float* W1r   = (const float*)d_in[6];
    const float* W2l   = (const float*)d_in[7];
    const float* b2    = (const float*)d_in[8];
    const float* W2r   = (const float*)d_in[9];
    const float* Wo    = (const float*)d_in[10];
    const float* bo    = (const float*)d_in[11];
    const int* src = ei;
    const int* dst = ei + N_EDGES;
    float* out = (float*)d_out;

    float *hA, *hB, *mean;
    cudaGetSymbolAddress((void**)&hA, g_hA);
    cudaGetSymbolAddress((void**)&hB, g_hB);
    cudaGetSymbolAddress((void**)&mean, g_mean);

    // CSR build (per launch; deterministic up to fp-irrelevant edge permutation)
    k_zero_deg<<<(N_NODES + 255) / 256, 256>>>();
    k_hist<<<(N_EDGES + 255) / 256, 256>>>(dst);
    k_scan1<<<SCAN_NB, SCAN_BS>>>();
    k_scan2<<<1, 1>>>();
    k_scan3<<<SCAN_NB, SCAN_BS>>>();
    k_fill<<<(N_EDGES + 255) / 256, 256>>>(src, dst);

    // h0 = emb[x]
    k_embed<<<(N_NODES * 16 + 255) / 256, 256>>>(x, emb, hA);

    // conv1
    k_agg<<<(N_NODES * 32 + 255) / 256, 256>>>(hA, mean);
    k_mm<<<(N_NODES + 255) / 256, 256>>>(mean, hA, W1l, W1r, b1, hB);

    // conv2
    k_agg<<<(N_NODES * 32 + 255) / 256, 256>>>(hB, mean);
    k_mm<<<(N_NODES + 255) / 256, 256>>>(mean, hB, W2l, W2r, b2, hA);

    // pool + head
    k_pool<<<(N_GRAPHS * 32 + 255) / 256, 256>>>(hA, batch, Wo, bo, out);
}

// round 2
// speedup vs baseline: 1.3350x; 1.3350x over previous
#include <cuda_runtime.h>

#define N_NODES 100000
#define N_EDGES 1000000
#define N_GRAPHS 2048
#define SCAN_BS 512
#define SCAN_NB ((N_NODES + SCAN_BS - 1) / SCAN_BS)

typedef unsigned long long u64;

// ---------------- device scratch (no allocs allowed) ----------------
__device__ float g_hA[N_NODES * 64];
__device__ float g_hB[N_NODES * 64];
__device__ float g_mean[N_NODES * 64];
__device__ int   g_deg[N_NODES];
__device__ int   g_rowptr[N_NODES + 1];
__device__ int   g_cursor[N_NODES];
__device__ int   g_colsrc[N_EDGES];
__device__ int   g_bsum[SCAN_NB];

// ---------------- f32x2 packed-FMA helpers (Blackwell FFMA2) ----------------
__device__ __forceinline__ u64 pk2(float x) {
    u64 r; asm("mov.b64 %0, {%1, %1};" : "=l"(r) : "f"(x)); return r;
}
__device__ __forceinline__ void fma2(u64 &d, u64 a, u64 b) {
    asm("fma.rn.f32x2 %0, %1, %2, %0;" : "+l"(d) : "l"(a), "l"(b));
}
__device__ __forceinline__ float2 up2(u64 v) {
    float lo, hi; asm("mov.b64 {%0, %1}, %2;" : "=f"(lo), "=f"(hi) : "l"(v));
    float2 f; f.x = lo; f.y = hi; return f;
}

// ---------------- embedding gather + degree zero (fused) ----------------
__global__ void k_embedzero(const int* __restrict__ x, const float* __restrict__ emb,
                            float* __restrict__ out) {
    int i = blockIdx.x * blockDim.x + threadIdx.x;
    if (i < N_NODES) g_deg[i] = 0;
    if (i >= N_NODES * 16) return;
    int n = i >> 4, q = i & 15;
    ((float4*)out)[i] = ((const float4*)emb)[(__ldg(x + n) << 4) + q];
}

__global__ void k_hist(const int* __restrict__ dst) {
    int e = blockIdx.x * blockDim.x + threadIdx.x;
    if (e < N_EDGES) atomicAdd(&g_deg[dst[e]], 1);
}

__global__ void k_scan1() {
    __shared__ int s[SCAN_BS];
    int i = blockIdx.x * SCAN_BS + threadIdx.x;
    s[threadIdx.x] = (i < N_NODES) ? g_deg[i] : 0;
    __syncthreads();
    for (int off = SCAN_BS / 2; off; off >>= 1) {
        if (threadIdx.x < off) s[threadIdx.x] += s[threadIdx.x + off];
        __syncthreads();
    }
    if (threadIdx.x == 0) g_bsum[blockIdx.x] = s[0];
}

// block-sum prefix computed in-block (replaces serial k_scan2) + intra-block scan
__global__ void k_scan3b() {
    __shared__ int s[SCAN_BS];
    int t = threadIdx.x;
    // 1) exclusive prefix of block sums: sum of g_bsum[b] for b < blockIdx.x
    int pv = 0;
    if (t < SCAN_NB && t < blockIdx.x) pv = g_bsum[t];
    s[t] = pv;
    __syncthreads();
    for (int off = SCAN_BS / 2; off; off >>= 1) {
        if (t < off) s[t] += s[t + off];
        __syncthreads();
    }
    int prefix = s[0];
    __syncthreads();
    // 2) intra-block inclusive scan of degrees
    int i = blockIdx.x * SCAN_BS + t;
    int v = (i < N_NODES) ? g_deg[i] : 0;
    s[t] = v;
    __syncthreads();
    for (int off = 1; off < SCAN_BS; off <<= 1) {
        int x = (t >= off) ? s[t - off] : 0;
        __syncthreads();
        s[t] += x;
        __syncthreads();
    }
    int excl = s[t] - v + prefix;
    if (i < N_NODES) {
        g_rowptr[i] = excl;
        g_cursor[i] = excl;
        if (i == N_NODES - 1) g_rowptr[N_NODES] = excl + v;
    }
}

__global__ void k_fill(const int* __restrict__ src, const int* __restrict__ dst) {
    int e = blockIdx.x * blockDim.x + threadIdx.x;
    if (e >= N_EDGES) return;
    int p = atomicAdd(&g_cursor[dst[e]], 1);
    g_colsrc[p] = src[e];
}

// ---------------- neighbor mean aggregation (warp per node) ----------------
__global__ void k_agg(const float* __restrict__ h, float* __restrict__ mean) {
    int w = (blockIdx.x * blockDim.x + threadIdx.x) >> 5;
    if (w >= N_NODES) return;
    int lane = threadIdx.x & 31;
    int s = g_rowptr[w], e = g_rowptr[w + 1];
    float ax = 0.f, ay = 0.f;
    int i = s;
    for (; i + 4 <= e; i += 4) {
        int u0 = g_colsrc[i], u1 = g_colsrc[i + 1], u2 = g_colsrc[i + 2], u3 = g_colsrc[i + 3];
        float2 v0 = *(const float2*)(h + u0 * 64 + lane * 2);
        float2 v1 = *(const float2*)(h + u1 * 64 + lane * 2);
        float2 v2 = *(const float2*)(h + u2 * 64 + lane * 2);
        float2 v3 = *(const float2*)(h + u3 * 64 + lane * 2);
        ax += v0.x + v1.x + v2.x + v3.x;
        ay += v0.y + v1.y + v2.y + v3.y;
    }
    for (; i < e; ++i) {
        int u = g_colsrc[i];
        float2 v = *(const float2*)(h + u * 64 + lane * 2);
        ax += v.x; ay += v.y;
    }
    float inv = 1.f / (float)max(e - s, 1);
    float2 o; o.x = ax * inv; o.y = ay * inv;
    *(float2*)(mean + w * 64 + lane * 2) = o;
}

// ---------------- fused dual GEMM + bias + relu ----------------
// out[n,:] = relu(mean[n,:] @ Wl + h[n,:] @ Wr + b). One thread per node,
// 32 packed f32x2 accumulators, weights staged in shared (LDS.128 broadcast),
// activations loaded as float4 (avoids 8x sector inflation of scalar loads).
__global__ void __launch_bounds__(256)
k_mm(const float* __restrict__ Am, const float* __restrict__ Ah,
     const float* __restrict__ Wl, const float* __restrict__ Wr,
     const float* __restrict__ bias, float* __restrict__ out) {
    __shared__ ulonglong2 sWl[64 * 16];
    __shared__ ulonglong2 sWr[64 * 16];
    __shared__ u64 sB[32];
    int t = threadIdx.x;
    const ulonglong2* gWl = (const ulonglong2*)Wl;
    const ulonglong2* gWr = (const ulonglong2*)Wr;
    for (int i = t; i < 1024; i += 256) { sWl[i] = gWl[i]; sWr[i] = gWr[i]; }
    if (t < 32) sB[t] = ((const u64*)bias)[t];
    __syncthreads();
    int n = blockIdx.x * 256 + t;
    if (n >= N_NODES) return;

    u64 acc[32];
#pragma unroll
    for (int j = 0; j < 32; j++) acc[j] = sB[j];

    const float4* am4 = (const float4*)(Am + n * 64);
    const float4* ah4 = (const float4*)(Ah + n * 64);
#pragma unroll 4
    for (int k0 = 0; k0 < 16; k0++) {
        float4 a4 = __ldg(am4 + k0);
        float4 c4 = __ldg(ah4 + k0);
        float av[4] = {a4.x, a4.y, a4.z, a4.w};
        float cv[4] = {c4.x, c4.y, c4.z, c4.w};
#pragma unroll
        for (int kk = 0; kk < 4; kk++) {
            u64 a2 = pk2(av[kk]);
            u64 c2 = pk2(cv[kk]);
            const ulonglong2* wl = sWl + (k0 * 4 + kk) * 16;
            const ulonglong2* wr = sWr + (k0 * 4 + kk) * 16;
#pragma unroll
            for (int j = 0; j < 16; j++) {
                ulonglong2 l = wl[j], r = wr[j];
                fma2(acc[2 * j],     a2, l.x);
                fma2(acc[2 * j + 1], a2, l.y);
                fma2(acc[2 * j],     c2, r.x);
                fma2(acc[2 * j + 1], c2, r.y);
            }
        }
    }

    float4* o4 = (float4*)(out + n * 64);
#pragma unroll
    for (int j = 0; j < 16; j++) {
        float2 p = up2(acc[2 * j]);
        float2 q = up2(acc[2 * j + 1]);
        float4 o;
        o.x = fmaxf(p.x, 0.f); o.y = fmaxf(p.y, 0.f);
        o.z = fmaxf(q.x, 0.f); o.w = fmaxf(q.y, 0.f);
        o4[j] = o;
    }
}

// ---------------- fused mean-pool + output head (warp per graph) ----------------
__global__ void k_pool(const float* __restrict__ h, const int* __restrict__ batch,
                       const float* __restrict__ Wout, const float* __restrict__ bout,
                       float* __restrict__ out) {
    int g = (blockIdx.x * blockDim.x + threadIdx.x) >> 5;
    if (g >= N_GRAPHS) return;
    int lane = threadIdx.x & 31;
    int s, e;
    { int lo = 0, hi = N_NODES;
      while (lo < hi) { int m = (lo + hi) >> 1; if (__ldg(batch + m) < g) lo = m + 1; else hi = m; }
      s = lo; }
    { int lo = s, hi = N_NODES;
      while (lo < hi) { int m = (lo + hi) >> 1; if (__ldg(batch + m) < g + 1) lo = m + 1; else hi = m; }
      e = lo; }
    float a0 = 0.f, a1 = 0.f;
    for (int n = s; n < e; ++n) {
        a0 += h[n * 64 + lane];
        a1 += h[n * 64 + lane + 32];
    }
    float inv = 1.f / (float)max(e - s, 1);
    a0 *= inv; a1 *= inv;
    float p0 = a0 * __ldg(Wout + lane * 2 + 0) + a1 * __ldg(Wout + (lane + 32) * 2 + 0);
    float p1 = a0 * __ldg(Wout + lane * 2 + 1) + a1 * __ldg(Wout + (lane + 32) * 2 + 1);
#pragma unroll
    for (int off = 16; off; off >>= 1) {
        p0 += __shfl_xor_sync(0xffffffffu, p0, off);
        p1 += __shfl_xor_sync(0xffffffffu, p1, off);
    }
    if (lane == 0) {
        out[g * 2 + 0] = p0 + __ldg(bout + 0);
        out[g * 2 + 1] = p1 + __ldg(bout + 1);
    }
}

// ---------------- launch ----------------
extern "C" void kernel_launch(void* const* d_in, const int* in_sizes, int n_in,
                              void* d_out, int out_size) {
    const int*   x     = (const int*)d_in[0];
    const int*   ei    = (const int*)d_in[1];
    const int*   batch = (const int*)d_in[2];
    const float* emb   = (const float*)d_in[3];
    const float* W1l   = (const float*)d_in[4];
    const float* b1    = (const float*)d_in[5];
    const float* W1r   = (const float*)d_in[6];
    const float* W2l   = (const float*)d_in[7];
    const float* b2    = (const float*)d_in[8];
    const float* W2r   = (const float*)d_in[9];
    const float* Wo    = (const float*)d_in[10];
    const float* bo    = (const float*)d_in[11];
    const int* src = ei;
    const int* dst = ei + N_EDGES;
    float* out = (float*)d_out;

    float *hA, *hB, *mean;
    cudaGetSymbolAddress((void**)&hA, g_hA);
    cudaGetSymbolAddress((void**)&hB, g_hB);
    cudaGetSymbolAddress((void**)&mean, g_mean);

    // 1: embed + zero degrees
    k_embedzero<<<(N_NODES * 16 + 255) / 256, 256>>>(x, emb, hA);
    // 2-5: CSR build
    k_hist<<<(N_EDGES + 255) / 256, 256>>>(dst);
    k_scan1<<<SCAN_NB, SCAN_BS>>>();
    k_scan3b<<<SCAN_NB, SCAN_BS>>>();
    k_fill<<<(N_EDGES + 255) / 256, 256>>>(src, dst);

    // 6-7: conv1  (launch #6 = k_agg -> ncu capture target)
    k_agg<<<(N_NODES * 32 + 255) / 256, 256>>>(hA, mean);
    k_mm<<<(N_NODES + 255) / 256, 256>>>(mean, hA, W1l, W1r, b1, hB);

    // 8-9: conv2
    k_agg<<<(N_NODES * 32 + 255) / 256, 256>>>(hB, mean);
    k_mm<<<(N_NODES + 255) / 256, 256>>>(mean, hB, W2l, W2r, b2, hA);

    // 10: pool + head
    k_pool<<<(N_GRAPHS * 32 + 255) / 256, 256>>>(hA, batch, Wo, bo, out);
}

// round 3
// speedup vs baseline: 1.3584x; 1.0175x over previous
#include <cuda_runtime.h>

#define N_NODES 100000
#define N_EDGES 1000000
#define N_GRAPHS 2048
#define SCAN_BS 512
#define SCAN_NB ((N_NODES + SCAN_BS - 1) / SCAN_BS)

typedef unsigned long long u64;

// ---------------- device scratch (no allocs allowed) ----------------
__device__ float g_hA[N_NODES * 64];
__device__ float g_hB[N_NODES * 64];
__device__ float g_mean[N_NODES * 64];
__device__ int   g_deg[N_NODES];          // INVARIANT: zero at kernel_launch entry
__device__ int   g_rowptr[N_NODES + 1];
__device__ int   g_cursor[N_NODES];
__device__ int   g_colsrc[N_EDGES];
__device__ u64   g_lb[SCAN_NB];           // lookback state: (flag<<32)|sum, zeroed by launch #1

// ---------------- f32x2 packed-FMA helpers (Blackwell FFMA2) ----------------
__device__ __forceinline__ u64 pk2(float x) {
    u64 r; asm("mov.b64 %0, {%1, %1};" : "=l"(r) : "f"(x)); return r;
}
__device__ __forceinline__ void fma2(u64 &d, u64 a, u64 b) {
    asm("fma.rn.f32x2 %0, %1, %2, %0;" : "+l"(d) : "l"(a), "l"(b));
}
__device__ __forceinline__ float2 up2(u64 v) {
    float lo, hi; asm("mov.b64 {%0, %1}, %2;" : "=f"(lo), "=f"(hi) : "l"(v));
    float2 f; f.x = lo; f.y = hi; return f;
}

// ---------------- launch 1: embed gather + dst histogram + lookback reset ----
// g_deg is guaranteed zero at entry (zero-init at load; re-zeroed by k_fill each call).
__global__ void k_embedhist(const int* __restrict__ x, const float* __restrict__ emb,
                            float* __restrict__ out, const int* __restrict__ dst) {
    int i = blockIdx.x * blockDim.x + threadIdx.x;
    if (i < SCAN_NB) g_lb[i] = 0ULL;
    if (i < N_EDGES) atomicAdd(&g_deg[dst[i]], 1);
    if (i < N_NODES * 16) {
        int n = i >> 4, q = i & 15;
        ((float4*)out)[i] = ((const float4*)emb)[(__ldg(x + n) << 4) + q];
    }
}

// ---------------- launch 2: single-pass decoupled-lookback scan ----------------
__global__ void __launch_bounds__(SCAN_BS) k_scanlb() {
    __shared__ int s[SCAN_BS];
    __shared__ int s_prefix;
    int t = threadIdx.x, bid = blockIdx.x;
    int i = bid * SCAN_BS + t;
    int v = (i < N_NODES) ? g_deg[i] : 0;
    // intra-block inclusive scan
    s[t] = v;
    __syncthreads();
    for (int off = 1; off < SCAN_BS; off <<= 1) {
        int x = (t >= off) ? s[t - off] : 0;
        __syncthreads();
        s[t] += x;
        __syncthreads();
    }
    int incl = s[t];
    int total = s[SCAN_BS - 1];

    // warp 0 resolves the exclusive prefix via lookback
    if (t < 32) {
        unsigned prefix = 0;
        if (bid == 0) {
            if (t == 0) atomicExch(&g_lb[0], (2ULL << 32) | (unsigned)total);
        } else {
            if (t == 0) atomicExch(&g_lb[bid], (1ULL << 32) | (unsigned)total);
            int p = bid - 1;
            while (true) {
                int idx = p - t;
                u64 st = 0;
                if (idx >= 0) {
                    do { st = atomicAdd(&g_lb[idx], 0ULL); } while ((st >> 32) == 0);
                }
                unsigned pm = __ballot_sync(0xffffffffu, idx >= 0 && (st >> 32) == 2);
                unsigned val;
                if (pm) {
                    int closest = __ffs(pm) - 1;           // nearest predecessor with full prefix
                    val = (t <= closest) ? (unsigned)st : 0u;
                } else {
                    val = (idx >= 0) ? (unsigned)st : 0u;
                }
#pragma unroll
                for (int o = 16; o; o >>= 1) val += __shfl_xor_sync(0xffffffffu, val, o);
                prefix += val;
                if (pm) break;
                p -= 32;
            }
            if (t == 0) atomicExch(&g_lb[bid], (2ULL << 32) | (unsigned)(prefix + (unsigned)total));
        }
        if (t == 0) s_prefix = (int)prefix;
    }
    __syncthreads();
    int excl = incl - v + s_prefix;
    if (i < N_NODES) {
        g_rowptr[i] = excl;
        g_cursor[i] = excl;
        if (i == N_NODES - 1) g_rowptr[N_NODES] = excl + v;
    }
}

// ---------------- launch 3: CSR fill + restore g_deg==0 invariant ----------------
__global__ void k_fill(const int* __restrict__ src, const int* __restrict__ dst) {
    int e = blockIdx.x * blockDim.x + threadIdx.x;
    if (e < N_NODES) g_deg[e] = 0;     // restore entry invariant for next call
    if (e >= N_EDGES) return;
    int p = atomicAdd(&g_cursor[dst[e]], 1);
    g_colsrc[p] = src[e];
}

// ---------------- neighbor mean aggregation (warp per node) ----------------
__global__ void k_agg(const float* __restrict__ h, float* __restrict__ mean) {
    int w = (blockIdx.x * blockDim.x + threadIdx.x) >> 5;
    if (w >= N_NODES) return;
    int lane = threadIdx.x & 31;
    int s = g_rowptr[w], e = g_rowptr[w + 1];
    float ax = 0.f, ay = 0.f;
    int i = s;
    for (; i + 4 <= e; i += 4) {
        int u0 = g_colsrc[i], u1 = g_colsrc[i + 1], u2 = g_colsrc[i + 2], u3 = g_colsrc[i + 3];
        float2 v0 = *(const float2*)(h + u0 * 64 + lane * 2);
        float2 v1 = *(const float2*)(h + u1 * 64 + lane * 2);
        float2 v2 = *(const float2*)(h + u2 * 64 + lane * 2);
        float2 v3 = *(const float2*)(h + u3 * 64 + lane * 2);
        ax += v0.x + v1.x + v2.x + v3.x;
        ay += v0.y + v1.y + v2.y + v3.y;
    }
    for (; i < e; ++i) {
        int u = g_colsrc[i];
        float2 v = *(const float2*)(h + u * 64 + lane * 2);
        ax += v.x; ay += v.y;
    }
    float inv = 1.f / (float)max(e - s, 1);
    float2 o; o.x = ax * inv; o.y = ay * inv;
    *(float2*)(mean + w * 64 + lane * 2) = o;
}

// ---------------- fused dual GEMM + bias + relu (thread per node) ----------------
__global__ void __launch_bounds__(256)
k_mm(const float* __restrict__ Am, const float* __restrict__ Ah,
     const float* __restrict__ Wl, const float* __restrict__ Wr,
     const float* __restrict__ bias, float* __restrict__ out) {
    __shared__ ulonglong2 sWl[64 * 16];
    __shared__ ulonglong2 sWr[64 * 16];
    __shared__ u64 sB[32];
    int t = threadIdx.x;
    const ulonglong2* gWl = (const ulonglong2*)Wl;
    const ulonglong2* gWr = (const ulonglong2*)Wr;
    for (int i = t; i < 1024; i += 256) { sWl[i] = gWl[i]; sWr[i] = gWr[i]; }
    if (t < 32) sB[t] = ((const u64*)bias)[t];
    __syncthreads();
    int n = blockIdx.x * 256 + t;
    if (n >= N_NODES) return;

    u64 acc[32];
#pragma unroll
    for (int j = 0; j < 32; j++) acc[j] = sB[j];

    const float4* am4 = (const float4*)(Am + n * 64);
    const float4* ah4 = (const float4*)(Ah + n * 64);
#pragma unroll 4
    for (int k0 = 0; k0 < 16; k0++) {
        float4 a4 = __ldg(am4 + k0);
        float4 c4 = __ldg(ah4 + k0);
        float av[4] = {a4.x, a4.y, a4.z, a4.w};
        float cv[4] = {c4.x, c4.y, c4.z, c4.w};
#pragma unroll
        for (int kk = 0; kk < 4; kk++) {
            u64 a2 = pk2(av[kk]);
            u64 c2 = pk2(cv[kk]);
            const ulonglong2* wl = sWl + (k0 * 4 + kk) * 16;
            const ulonglong2* wr = sWr + (k0 * 4 + kk) * 16;
#pragma unroll
            for (int j = 0; j < 16; j++) {
                ulonglong2 l = wl[j], r = wr[j];
                fma2(acc[2 * j],     a2, l.x);
                fma2(acc[2 * j + 1], a2, l.y);
                fma2(acc[2 * j],     c2, r.x);
                fma2(acc[2 * j + 1], c2, r.y);
            }
        }
    }

    float4* o4 = (float4*)(out + n * 64);
#pragma unroll
    for (int j = 0; j < 16; j++) {
        float2 p = up2(acc[2 * j]);
        float2 q = up2(acc[2 * j + 1]);
        float4 o;
        o.x = fmaxf(p.x, 0.f); o.y = fmaxf(p.y, 0.f);
        o.z = fmaxf(q.x, 0.f); o.w = fmaxf(q.y, 0.f);
        o4[j] = o;
    }
}

// ---------------- fused mean-pool + output head (warp per graph) ----------------
__global__ void k_pool(const float* __restrict__ h, const int* __restrict__ batch,
                       const float* __restrict__ Wout, const float* __restrict__ bout,
                       float* __restrict__ out) {
    int g = (blockIdx.x * blockDim.x + threadIdx.x) >> 5;
    if (g >= N_GRAPHS) return;
    int lane = threadIdx.x & 31;
    int s, e;
    { int lo = 0, hi = N_NODES;
      while (lo < hi) { int m = (lo + hi) >> 1; if (__ldg(batch + m) < g) lo = m + 1; else hi = m; }
      s = lo; }
    { int lo = s, hi = N_NODES;
      while (lo < hi) { int m = (lo + hi) >> 1; if (__ldg(batch + m) < g + 1) lo = m + 1; else hi = m; }
      e = lo; }
    float a0 = 0.f, a1 = 0.f;
    for (int n = s; n < e; ++n) {
        a0 += h[n * 64 + lane];
        a1 += h[n * 64 + lane + 32];
    }
    float inv = 1.f / (float)max(e - s, 1);
    a0 *= inv; a1 *= inv;
    float p0 = a0 * __ldg(Wout + lane * 2 + 0) + a1 * __ldg(Wout + (lane + 32) * 2 + 0);
    float p1 = a0 * __ldg(Wout + lane * 2 + 1) + a1 * __ldg(Wout + (lane + 32) * 2 + 1);
#pragma unroll
    for (int off = 16; off; off >>= 1) {
        p0 += __shfl_xor_sync(0xffffffffu, p0, off);
        p1 += __shfl_xor_sync(0xffffffffu, p1, off);
    }
    if (lane == 0) {
        out[g * 2 + 0] = p0 + __ldg(bout + 0);
        out[g * 2 + 1] = p1 + __ldg(bout + 1);
    }
}

// ---------------- launch ----------------
extern "C" void kernel_launch(void* const* d_in, const int* in_sizes, int n_in,
                              void* d_out, int out_size) {
    const int*   x     = (const int*)d_in[0];
    const int*   ei    = (const int*)d_in[1];
    const int*   batch = (const int*)d_in[2];
    const float* emb   = (const float*)d_in[3];
    const float* W1l   = (const float*)d_in[4];
    const float* b1    = (const float*)d_in[5];
    const float* W1r   = (const float*)d_in[6];
    const float* W2l   = (const float*)d_in[7];
    const float* b2    = (const float*)d_in[8];
    const float* W2r   = (const float*)d_in[9];
    const float* Wo    = (const float*)d_in[10];
    const float* bo    = (const float*)d_in[11];
    const int* src = ei;
    const int* dst = ei + N_EDGES;
    float* out = (float*)d_out;

    float *hA, *hB, *mean;
    cudaGetSymbolAddress((void**)&hA, g_hA);
    cudaGetSymbolAddress((void**)&hB, g_hB);
    cudaGetSymbolAddress((void**)&mean, g_mean);

    // 1: embed gather + dst histogram (+ lookback state reset)
    k_embedhist<<<(N_NODES * 16 + 255) / 256, 256>>>(x, emb, hA, dst);
    // 2: rowptr/cursor via single-pass lookback scan
    k_scanlb<<<SCAN_NB, SCAN_BS>>>();
    // 3: CSR fill (+ restore deg==0 invariant)
    k_fill<<<(N_EDGES + 255) / 256, 256>>>(src, dst);

    // 4: conv1 aggregation  <-- ncu capture slot
    k_agg<<<(N_NODES * 32 + 255) / 256, 256>>>(hA, mean);
    // 5: conv1 dense
    k_mm<<<(N_NODES + 255) / 256, 256>>>(mean, hA, W1l, W1r, b1, hB);

    // 6-7: conv2
    k_agg<<<(N_NODES * 32 + 255) / 256, 256>>>(hB, mean);
    k_mm<<<(N_NODES + 255) / 256, 256>>>(mean, hB, W2l, W2r, b2, hA);

    // 8: pool + head
    k_pool<<<(N_GRAPHS * 32 + 255) / 256, 256>>>(hA, batch, Wo, bo, out);
}

// round 4
// speedup vs baseline: 1.9373x; 1.4262x over previous
#include <cuda_runtime.h>

#define N_NODES 100000
#define N_EDGES 1000000
#define N_GRAPHS 2048
#define SCAN_BS 512
#define SCAN_NB ((N_NODES + SCAN_BS - 1) / SCAN_BS)

typedef unsigned long long u64;

// ---------------- device scratch (no allocs allowed) ----------------
__device__ float g_hA[N_NODES * 64];
__device__ float g_hB[N_NODES * 64];
__device__ float g_mean[N_NODES * 64];
__device__ float g_Ep[128 * 64];          // emb @ W1l
__device__ float g_Rp[128 * 64];          // emb @ W1r
__device__ int   g_deg[N_NODES];          // INVARIANT: zero at kernel_launch entry
__device__ int   g_rowptr[N_NODES + 1];
__device__ int   g_cursor[N_NODES];
__device__ int   g_colsrc[N_EDGES];
__device__ u64   g_lb[SCAN_NB];           // lookback state, zeroed by k_prep

// ---------------- f32x2 packed-FMA helpers ----------------
__device__ __forceinline__ u64 pk2(float x) {
    u64 r; asm("mov.b64 %0, {%1, %1};" : "=l"(r) : "f"(x)); return r;
}
__device__ __forceinline__ void fma2(u64 &d, u64 a, u64 b) {
    asm("fma.rn.f32x2 %0, %1, %2, %0;" : "+l"(d) : "l"(a), "l"(b));
}
__device__ __forceinline__ float2 up2(u64 v) {
    float lo, hi; asm("mov.b64 {%0, %1}, %2;" : "=f"(lo), "=f"(hi) : "l"(v));
    float2 f; f.x = lo; f.y = hi; return f;
}

// ---------------- launch 1: E'=emb@W1l, R'=emb@W1r (+ lookback reset) -------
__global__ void k_prep(const float* __restrict__ emb, const float* __restrict__ W1l,
                       const float* __restrict__ W1r) {
    __shared__ float se[64];
    int v = blockIdx.x;        // vocab row 0..127
    int t = threadIdx.x;       // 0..127
    if (v == 0) for (int i = t; i < SCAN_NB; i += 128) g_lb[i] = 0ULL;
    if (t < 64) se[t] = emb[v * 64 + t];
    __syncthreads();
    const float* W = (t < 64) ? W1l : W1r;
    int c = t & 63;
    float acc = 0.f;
#pragma unroll 8
    for (int k = 0; k < 64; k++) acc += se[k] * __ldg(W + k * 64 + c);
    if (t < 64) g_Ep[v * 64 + c] = acc; else g_Rp[v * 64 + c] = acc;
}

// ---------------- launch 2: gather E'[x] + dst histogram ----------------
__global__ void k_embedhist(const int* __restrict__ x, const int* __restrict__ dst,
                            float* __restrict__ out) {
    int i = blockIdx.x * blockDim.x + threadIdx.x;
    if (i < N_EDGES) atomicAdd(&g_deg[dst[i]], 1);
    if (i < N_NODES * 16) {
        int n = i >> 4, q = i & 15;
        ((float4*)out)[i] = ((const float4*)g_Ep)[(__ldg(x + n) << 4) + q];
    }
}

// ---------------- launch 3: single-pass decoupled-lookback scan -------------
__global__ void __launch_bounds__(SCAN_BS) k_scanlb() {
    __shared__ int s[SCAN_BS];
    __shared__ int s_prefix;
    int t = threadIdx.x, bid = blockIdx.x;
    int i = bid * SCAN_BS + t;
    int v = (i < N_NODES) ? g_deg[i] : 0;
    s[t] = v;
    __syncthreads();
    for (int off = 1; off < SCAN_BS; off <<= 1) {
        int x = (t >= off) ? s[t - off] : 0;
        __syncthreads();
        s[t] += x;
        __syncthreads();
    }
    int incl = s[t];
    int total = s[SCAN_BS - 1];
    if (t < 32) {
        unsigned prefix = 0;
        if (bid == 0) {
            if (t == 0) atomicExch(&g_lb[0], (2ULL << 32) | (unsigned)total);
        } else {
            if (t == 0) atomicExch(&g_lb[bid], (1ULL << 32) | (unsigned)total);
            int p = bid - 1;
            while (true) {
                int idx = p - t;
                u64 st = 0;
                if (idx >= 0) {
                    do { st = atomicAdd(&g_lb[idx], 0ULL); } while ((st >> 32) == 0);
                }
                unsigned pm = __ballot_sync(0xffffffffu, idx >= 0 && (st >> 32) == 2);
                unsigned val;
                if (pm) {
                    int closest = __ffs(pm) - 1;
                    val = (t <= closest) ? (unsigned)st : 0u;
                } else {
                    val = (idx >= 0) ? (unsigned)st : 0u;
                }
#pragma unroll
                for (int o = 16; o; o >>= 1) val += __shfl_xor_sync(0xffffffffu, val, o);
                prefix += val;
                if (pm) break;
                p -= 32;
            }
            if (t == 0) atomicExch(&g_lb[bid], (2ULL << 32) | (unsigned)(prefix + (unsigned)total));
        }
        if (t == 0) s_prefix = (int)prefix;
    }
    __syncthreads();
    int excl = incl - v + s_prefix;
    if (i < N_NODES) {
        g_rowptr[i] = excl;
        g_cursor[i] = excl;
        if (i == N_NODES - 1) g_rowptr[N_NODES] = excl + v;
    }
}

// ---------------- launch 4: CSR fill + restore deg invariant  [profile slot] -
__global__ void k_fill(const int* __restrict__ src, const int* __restrict__ dst) {
    int e = blockIdx.x * blockDim.x + threadIdx.x;
    if (e < N_NODES) g_deg[e] = 0;
    if (e >= N_EDGES) return;
    int p = atomicAdd(&g_cursor[dst[e]], 1);
    g_colsrc[p] = src[e];
}

// ---------------- aggregation core: half-warp per edge, float4 per lane -----
// lanes 0-15 handle even edge of a pair, lanes 16-31 the odd edge; each lane
// accumulates a float4 feature group; cross-half shfl reduce at the end.
__device__ __forceinline__ float4 agg_body(const float* __restrict__ h,
                                           int s, int e, int half, int fb) {
    float ax = 0.f, ay = 0.f, az = 0.f, aw = 0.f;
    int i = s;
    for (; i + 4 <= e; i += 4) {
        int u0 = __ldg(g_colsrc + i + half);
        int u1 = __ldg(g_colsrc + i + 2 + half);
        float4 v0 = *(const float4*)(h + u0 * 64 + fb);
        float4 v1 = *(const float4*)(h + u1 * 64 + fb);
        ax += v0.x + v1.x; ay += v0.y + v1.y;
        az += v0.z + v1.z; aw += v0.w + v1.w;
    }
    if (i + 2 <= e) {
        int u = __ldg(g_colsrc + i + half);
        float4 v = *(const float4*)(h + u * 64 + fb);
        ax += v.x; ay += v.y; az += v.z; aw += v.w;
        i += 2;
    }
    if (i < e && half == 0) {
        int u = __ldg(g_colsrc + i);
        float4 v = *(const float4*)(h + u * 64 + fb);
        ax += v.x; ay += v.y; az += v.z; aw += v.w;
    }
    ax += __shfl_xor_sync(0xffffffffu, ax, 16);
    ay += __shfl_xor_sync(0xffffffffu, ay, 16);
    az += __shfl_xor_sync(0xffffffffu, az, 16);
    aw += __shfl_xor_sync(0xffffffffu, aw, 16);
    float4 r; r.x = ax; r.y = ay; r.z = az; r.w = aw;
    return r;
}

// launch 5: conv1 fully fused — out = relu(mean(E'[x_src]) + R'[x_n] + b1)
__global__ void k_agg1(const float* __restrict__ h, const int* __restrict__ x,
                       const float* __restrict__ b1, float* __restrict__ out) {
    int w = (blockIdx.x * blockDim.x + threadIdx.x) >> 5;
    if (w >= N_NODES) return;
    int lane = threadIdx.x & 31;
    int half = lane >> 4;
    int fb = (lane & 15) * 4;
    int s = g_rowptr[w], e = g_rowptr[w + 1];
    float4 a = agg_body(h, s, e, half, fb);
    float inv = 1.f / (float)max(e - s, 1);
    int vid = __ldg(x + w);
    float4 r = *(const float4*)(g_Rp + vid * 64 + fb);
    float4 bb = *(const float4*)(b1 + fb);
    if (half == 0) {
        float4 o;
        o.x = fmaxf(a.x * inv + r.x + bb.x, 0.f);
        o.y = fmaxf(a.y * inv + r.y + bb.y, 0.f);
        o.z = fmaxf(a.z * inv + r.z + bb.z, 0.f);
        o.w = fmaxf(a.w * inv + r.w + bb.w, 0.f);
        *(float4*)(out + w * 64 + fb) = o;
    }
}

// launch 6: conv2 aggregation (plain mean)
__global__ void k_agg(const float* __restrict__ h, float* __restrict__ mean) {
    int w = (blockIdx.x * blockDim.x + threadIdx.x) >> 5;
    if (w >= N_NODES) return;
    int lane = threadIdx.x & 31;
    int half = lane >> 4;
    int fb = (lane & 15) * 4;
    int s = g_rowptr[w], e = g_rowptr[w + 1];
    float4 a = agg_body(h, s, e, half, fb);
    float inv = 1.f / (float)max(e - s, 1);
    if (half == 0) {
        float4 o; o.x = a.x * inv; o.y = a.y * inv; o.z = a.z * inv; o.w = a.w * inv;
        *(float4*)(mean + w * 64 + fb) = o;
    }
}

// ---------------- launch 7: conv2 dual GEMM + bias + relu -------------------
__global__ void __launch_bounds__(256)
k_mm(const float* __restrict__ Am, const float* __restrict__ Ah,
     const float* __restrict__ Wl, const float* __restrict__ Wr,
     const float* __restrict__ bias, float* __restrict__ out) {
    __shared__ ulonglong2 sWl[64 * 16];
    __shared__ ulonglong2 sWr[64 * 16];
    __shared__ u64 sB[32];
    int t = threadIdx.x;
    const ulonglong2* gWl = (const ulonglong2*)Wl;
    const ulonglong2* gWr = (const ulonglong2*)Wr;
    for (int i = t; i < 1024; i += 256) { sWl[i] = gWl[i]; sWr[i] = gWr[i]; }
    if (t < 32) sB[t] = ((const u64*)bias)[t];
    __syncthreads();
    int n = blockIdx.x * 256 + t;
    if (n >= N_NODES) return;

    u64 acc[32];
#pragma unroll
    for (int j = 0; j < 32; j++) acc[j] = sB[j];

    const float4* am4 = (const float4*)(Am + n * 64);
    const float4* ah4 = (const float4*)(Ah + n * 64);
#pragma unroll 4
    for (int k0 = 0; k0 < 16; k0++) {
        float4 a4 = __ldg(am4 + k0);
        float4 c4 = __ldg(ah4 + k0);
        float av[4] = {a4.x, a4.y, a4.z, a4.w};
        float cv[4] = {c4.x, c4.y, c4.z, c4.w};
#pragma unroll
        for (int kk = 0; kk < 4; kk++) {
            u64 a2 = pk2(av[kk]);
            u64 c2 = pk2(cv[kk]);
            const ulonglong2* wl = sWl + (k0 * 4 + kk) * 16;
            const ulonglong2* wr = sWr + (k0 * 4 + kk) * 16;
#pragma unroll
            for (int j = 0; j < 16; j++) {
                ulonglong2 l = wl[j], r = wr[j];
                fma2(acc[2 * j],     a2, l.x);
                fma2(acc[2 * j + 1], a2, l.y);
                fma2(acc[2 * j],     c2, r.x);
                fma2(acc[2 * j + 1], c2, r.y);
            }
        }
    }

    float4* o4 = (float4*)(out + n * 64);
#pragma unroll
    for (int j = 0; j < 16; j++) {
        float2 p = up2(acc[2 * j]);
        float2 q = up2(acc[2 * j + 1]);
        float4 o;
        o.x = fmaxf(p.x, 0.f); o.y = fmaxf(p.y, 0.f);
        o.z = fmaxf(q.x, 0.f); o.w = fmaxf(q.y, 0.f);
        o4[j] = o;
    }
}

// ---------------- launch 8: mean-pool + output head (warp per graph) --------
__global__ void k_pool(const float* __restrict__ h, const int* __restrict__ batch,
                       const float* __restrict__ Wout, const float* __restrict__ bout,
                       float* __restrict__ out) {
    int g = (blockIdx.x * blockDim.x + threadIdx.x) >> 5;
    if (g >= N_GRAPHS) return;
    int lane = threadIdx.x & 31;
    int s, e;
    { int lo = 0, hi = N_NODES;
      while (lo < hi) { int m = (lo + hi) >> 1; if (__ldg(batch + m) < g) lo = m + 1; else hi = m; }
      s = lo; }
    { int lo = s, hi = N_NODES;
      while (lo < hi) { int m = (lo + hi) >> 1; if (__ldg(batch + m) < g + 1) lo = m + 1; else hi = m; }
      e = lo; }
    float a0 = 0.f, a1 = 0.f;
    for (int n = s; n < e; ++n) {
        a0 += h[n * 64 + lane];
        a1 += h[n * 64 + lane + 32];
    }
    float inv = 1.f / (float)max(e - s, 1);
    a0 *= inv; a1 *= inv;
    float p0 = a0 * __ldg(Wout + lane * 2 + 0) + a1 * __ldg(Wout + (lane + 32) * 2 + 0);
    float p1 = a0 * __ldg(Wout + lane * 2 + 1) + a1 * __ldg(Wout + (lane + 32) * 2 + 1);
#pragma unroll
    for (int off = 16; off; off >>= 1) {
        p0 += __shfl_xor_sync(0xffffffffu, p0, off);
        p1 += __shfl_xor_sync(0xffffffffu, p1, off);
    }
    if (lane == 0) {
        out[g * 2 + 0] = p0 + __ldg(bout + 0);
        out[g * 2 + 1] = p1 + __ldg(bout + 1);
    }
}

// ---------------- launch ----------------
extern "C" void kernel_launch(void* const* d_in, const int* in_sizes, int n_in,
                              void* d_out, int out_size) {
    const int*   x     = (const int*)d_in[0];
    const int*   ei    = (const int*)d_in[1];
    const int*   batch = (const int*)d_in[2];
    const float* emb   = (const float*)d_in[3];
    const float* W1l   = (const float*)d_in[4];
    const float* b1    = (const float*)d_in[5];
    const float* W1r   = (const float*)d_in[6];
    const float* W2l   = (const float*)d_in[7];
    const float* b2    = (const float*)d_in[8];
    const float* W2r   = (const float*)d_in[9];
    const float* Wo    = (const float*)d_in[10];
    const float* bo    = (const float*)d_in[11];
    const int* src = ei;
    const int* dst = ei + N_EDGES;
    float* out = (float*)d_out;

    float *hA, *hB, *mean;
    cudaGetSymbolAddress((void**)&hA, g_hA);
    cudaGetSymbolAddress((void**)&hB, g_hB);
    cudaGetSymbolAddress((void**)&mean, g_mean);

    // 1: tiny weight transform E'=emb@W1l, R'=emb@W1r (+ lb reset)
    k_prep<<<128, 128>>>(emb, W1l, W1r);
    // 2: gather hA = E'[x] + dst histogram
    k_embedhist<<<(N_NODES * 16 + 255) / 256, 256>>>(x, dst, hA);
    // 3: rowptr/cursor via lookback scan
    k_scanlb<<<SCAN_NB, SCAN_BS>>>();
    // 4: CSR fill (+ restore deg==0)            <-- ncu capture slot
    k_fill<<<(N_EDGES + 255) / 256, 256>>>(src, dst);

    // 5: conv1 fully fused (agg + R'[x] + b1 + relu)
    k_agg1<<<(N_NODES * 32 + 255) / 256, 256>>>(hA, x, b1, hB);

    // 6-7: conv2
    k_agg<<<(N_NODES * 32 + 255) / 256, 256>>>(hB, mean);
    k_mm<<<(N_NODES + 255) / 256, 256>>>(mean, hB, W2l, W2r, b2, hA);

    // 8: pool + head
    k_pool<<<(N_GRAPHS * 32 + 255) / 256, 256>>>(hA, batch, Wo, bo, out);
}

// round 6
// speedup vs baseline: 2.0580x; 1.0623x over previous
#include <cuda_runtime.h>

#define N_NODES 100000
#define N_EDGES 1000000
#define N_GRAPHS 2048
#define SCAN_BS 512
#define SCAN_NB ((N_NODES + SCAN_BS - 1) / SCAN_BS)

typedef unsigned long long u64;

// ---------------- device scratch (no allocs allowed) ----------------
__device__ float g_hA[N_NODES * 64];
__device__ float g_hB[N_NODES * 64];
__device__ float g_mean[N_NODES * 64];
__device__ float g_Ep[128 * 64];          // emb @ W1l  (32 KB, L1-resident)
__device__ float g_Rp[128 * 64];          // emb @ W1r
__device__ int   g_deg[N_NODES];          // INVARIANT: zero at kernel_launch entry
__device__ int   g_rowptr[N_NODES + 1];
__device__ int   g_cursor[N_NODES];
__device__ int   g_colsrc[N_EDGES];       // packed: src_node | (vocab_id << 20)
__device__ u64   g_lb[SCAN_NB];

// ---------------- f32x2 packed-FMA helpers ----------------
__device__ __forceinline__ u64 pk2(float x) {
    u64 r; asm("mov.b64 %0, {%1, %1};" : "=l"(r) : "f"(x)); return r;
}
__device__ __forceinline__ void fma2(u64 &d, u64 a, u64 b) {
    asm("fma.rn.f32x2 %0, %1, %2, %0;" : "+l"(d) : "l"(a), "l"(b));
}
__device__ __forceinline__ float2 up2(u64 v) {
    float lo, hi; asm("mov.b64 {%0, %1}, %2;" : "=f"(lo), "=f"(hi) : "l"(v));
    float2 f; f.x = lo; f.y = hi; return f;
}

// ---------- launch 1: E'=emb@W1l, R'=emb@W1r  +  dst histogram + lb reset ----
__global__ void k_prep(const float* __restrict__ emb, const float* __restrict__ W1l,
                       const float* __restrict__ W1r, const int* __restrict__ dst) {
    int b = blockIdx.x, t = threadIdx.x;
    if (b < 128) {
        __shared__ float se[64];
        if (b == 0) for (int i = t; i < SCAN_NB; i += 128) g_lb[i] = 0ULL;
        if (t < 64) se[t] = emb[b * 64 + t];
        __syncthreads();
        const float* W = (t < 64) ? W1l : W1r;
        int c = t & 63;
        float acc = 0.f;
#pragma unroll 8
        for (int k = 0; k < 64; k++) acc += se[k] * __ldg(W + k * 64 + c);
        if (t < 64) g_Ep[b * 64 + c] = acc; else g_Rp[b * 64 + c] = acc;
    } else {
        // each histogram block covers 512 edges (256 threads x 2)
        int base = (b - 128) * 512;                 // FIX: was *256 (overlap bug)
        int e0 = base + 2 * t;
        if (e0 < N_EDGES) atomicAdd(&g_deg[__ldg(dst + e0)], 1);
        if (e0 + 1 < N_EDGES) atomicAdd(&g_deg[__ldg(dst + e0 + 1)], 1);
    }
}

// ---------------- launch 2: single-pass decoupled-lookback scan -------------
__global__ void __launch_bounds__(SCAN_BS) k_scanlb() {
    __shared__ int s[SCAN_BS];
    __shared__ int s_prefix;
    int t = threadIdx.x, bid = blockIdx.x;
    int i = bid * SCAN_BS + t;
    int v = (i < N_NODES) ? g_deg[i] : 0;
    s[t] = v;
    __syncthreads();
    for (int off = 1; off < SCAN_BS; off <<= 1) {
        int x = (t >= off) ? s[t - off] : 0;
        __syncthreads();
        s[t] += x;
        __syncthreads();
    }
    int incl = s[t];
    int total = s[SCAN_BS - 1];
    if (t < 32) {
        unsigned prefix = 0;
        if (bid == 0) {
            if (t == 0) atomicExch(&g_lb[0], (2ULL << 32) | (unsigned)total);
        } else {
            if (t == 0) atomicExch(&g_lb[bid], (1ULL << 32) | (unsigned)total);
            int p = bid - 1;
            while (true) {
                int idx = p - t;
                u64 st = 0;
                if (idx >= 0) {
                    do { st = atomicAdd(&g_lb[idx], 0ULL); } while ((st >> 32) == 0);
                }
                unsigned pm = __ballot_sync(0xffffffffu, idx >= 0 && (st >> 32) == 2);
                unsigned val;
                if (pm) {
                    int closest = __ffs(pm) - 1;
                    val = (t <= closest) ? (unsigned)st : 0u;
                } else {
                    val = (idx >= 0) ? (unsigned)st : 0u;
                }
#pragma unroll
                for (int o = 16; o; o >>= 1) val += __shfl_xor_sync(0xffffffffu, val, o);
                prefix += val;
                if (pm) break;
                p -= 32;
            }
            if (t == 0) atomicExch(&g_lb[bid], (2ULL << 32) | (unsigned)(prefix + (unsigned)total));
        }
        if (t == 0) s_prefix = (int)prefix;
    }
    __syncthreads();
    int excl = incl - v + s_prefix;
    if (i < N_NODES) {
        g_rowptr[i] = excl;
        g_cursor[i] = excl;
        if (i == N_NODES - 1) g_rowptr[N_NODES] = excl + v;
    }
}

// ------- launch 3: CSR fill (packed node|vid) + restore deg invariant -------
__global__ void k_fill(const int* __restrict__ src, const int* __restrict__ dst,
                       const int* __restrict__ x) {
    int e = blockIdx.x * blockDim.x + threadIdx.x;
    if (e < N_NODES) g_deg[e] = 0;
    if (e >= N_EDGES) return;
    int sn = __ldg(src + e);
    int packed = sn | (__ldg(x + sn) << 20);
    int p = atomicAdd(&g_cursor[dst[e]], 1);
    g_colsrc[p] = packed;
}

// ---------------- aggregation core (templated row lookup) -------------------
// half-warp per edge, float4 per lane. UseVid: rows come from 32KB E' table.
template <bool UseVid>
__device__ __forceinline__ float4 agg_body(const float* __restrict__ base,
                                           int s, int e, int half, int fb) {
    float ax = 0.f, ay = 0.f, az = 0.f, aw = 0.f;
    int i = s;
    for (; i + 4 <= e; i += 4) {
        int u0 = __ldg(g_colsrc + i + half);
        int u1 = __ldg(g_colsrc + i + 2 + half);
        int r0 = UseVid ? (u0 >> 20) : (u0 & 0xFFFFF);
        int r1 = UseVid ? (u1 >> 20) : (u1 & 0xFFFFF);
        float4 v0 = *(const float4*)(base + r0 * 64 + fb);
        float4 v1 = *(const float4*)(base + r1 * 64 + fb);
        ax += v0.x + v1.x; ay += v0.y + v1.y;
        az += v0.z + v1.z; aw += v0.w + v1.w;
    }
    if (i + 2 <= e) {
        int u = __ldg(g_colsrc + i + half);
        int r = UseVid ? (u >> 20) : (u & 0xFFFFF);
        float4 v = *(const float4*)(base + r * 64 + fb);
        ax += v.x; ay += v.y; az += v.z; aw += v.w;
        i += 2;
    }
    if (i < e && half == 0) {
        int u = __ldg(g_colsrc + i);
        int r = UseVid ? (u >> 20) : (u & 0xFFFFF);
        float4 v = *(const float4*)(base + r * 64 + fb);
        ax += v.x; ay += v.y; az += v.z; aw += v.w;
    }
    ax += __shfl_xor_sync(0xffffffffu, ax, 16);
    ay += __shfl_xor_sync(0xffffffffu, ay, 16);
    az += __shfl_xor_sync(0xffffffffu, az, 16);
    aw += __shfl_xor_sync(0xffffffffu, aw, 16);
    float4 r; r.x = ax; r.y = ay; r.z = az; r.w = aw;
    return r;
}

// launch 4 [capture slot]: conv1 fully fused — relu(mean(E'[vid]) + R'[x_n] + b1)
__global__ void k_agg1(const int* __restrict__ x, const float* __restrict__ b1,
                       float* __restrict__ out) {
    int w = (blockIdx.x * blockDim.x + threadIdx.x) >> 5;
    if (w >= N_NODES) return;
    int lane = threadIdx.x & 31;
    int half = lane >> 4;
    int fb = (lane & 15) * 4;
    int s = g_rowptr[w], e = g_rowptr[w + 1];
    float4 a = agg_body<true>(g_Ep, s, e, half, fb);
    if (half == 0) {
        float inv = 1.f / (float)max(e - s, 1);
        int vid = __ldg(x + w);
        float4 r = *(const float4*)(g_Rp + vid * 64 + fb);
        float4 bb = *(const float4*)(b1 + fb);
        float4 o;
        o.x = fmaxf(fmaf(a.x, inv, r.x + bb.x), 0.f);
        o.y = fmaxf(fmaf(a.y, inv, r.y + bb.y), 0.f);
        o.z = fmaxf(fmaf(a.z, inv, r.z + bb.z), 0.f);
        o.w = fmaxf(fmaf(a.w, inv, r.w + bb.w), 0.f);
        *(float4*)(out + w * 64 + fb) = o;
    }
}

// launch 5: conv2 aggregation (plain mean over node rows)
__global__ void k_agg(const float* __restrict__ h, float* __restrict__ mean) {
    int w = (blockIdx.x * blockDim.x + threadIdx.x) >> 5;
    if (w >= N_NODES) return;
    int lane = threadIdx.x & 31;
    int half = lane >> 4;
    int fb = (lane & 15) * 4;
    int s = g_rowptr[w], e = g_rowptr[w + 1];
    float4 a = agg_body<false>(h, s, e, half, fb);
    if (half == 0) {
        float inv = 1.f / (float)max(e - s, 1);
        float4 o; o.x = a.x * inv; o.y = a.y * inv; o.z = a.z * inv; o.w = a.w * inv;
        *(float4*)(mean + w * 64 + fb) = o;
    }
}

// ---------------- launch 6: conv2 dual GEMM + bias + relu -------------------
__global__ void __launch_bounds__(256)
k_mm(const float* __restrict__ Am, const float* __restrict__ Ah,
     const float* __restrict__ Wl, const float* __restrict__ Wr,
     const float* __restrict__ bias, float* __restrict__ out) {
    __shared__ ulonglong2 sWl[64 * 16];
    __shared__ ulonglong2 sWr[64 * 16];
    __shared__ u64 sB[32];
    int t = threadIdx.x;
    const ulonglong2* gWl = (const ulonglong2*)Wl;
    const ulonglong2* gWr = (const ulonglong2*)Wr;
    for (int i = t; i < 1024; i += 256) { sWl[i] = gWl[i]; sWr[i] = gWr[i]; }
    if (t < 32) sB[t] = ((const u64*)bias)[t];
    __syncthreads();
    int n = blockIdx.x * 256 + t;
    if (n >= N_NODES) return;

    u64 acc[32];
#pragma unroll
    for (int j = 0; j < 32; j++) acc[j] = sB[j];

    const float4* am4 = (const float4*)(Am + n * 64);
    const float4* ah4 = (const float4*)(Ah + n * 64);
#pragma unroll 4
    for (int k0 = 0; k0 < 16; k0++) {
        float4 a4 = __ldg(am4 + k0);
        float4 c4 = __ldg(ah4 + k0);
        float av[4] = {a4.x, a4.y, a4.z, a4.w};
        float cv[4] = {c4.x, c4.y, c4.z, c4.w};
#pragma unroll
        for (int kk = 0; kk < 4; kk++) {
            u64 a2 = pk2(av[kk]);
            u64 c2 = pk2(cv[kk]);
            const ulonglong2* wl = sWl + (k0 * 4 + kk) * 16;
            const ulonglong2* wr = sWr + (k0 * 4 + kk) * 16;
#pragma unroll
            for (int j = 0; j < 16; j++) {
                ulonglong2 l = wl[j], r = wr[j];
                fma2(acc[2 * j],     a2, l.x);
                fma2(acc[2 * j + 1], a2, l.y);
                fma2(acc[2 * j],     c2, r.x);
                fma2(acc[2 * j + 1], c2, r.y);
            }
        }
    }

    float4* o4 = (float4*)(out + n * 64);
#pragma unroll
    for (int j = 0; j < 16; j++) {
        float2 p = up2(acc[2 * j]);
        float2 q = up2(acc[2 * j + 1]);
        float4 o;
        o.x = fmaxf(p.x, 0.f); o.y = fmaxf(p.y, 0.f);
        o.z = fmaxf(q.x, 0.f); o.w = fmaxf(q.y, 0.f);
        o4[j] = o;
    }
}

// ---------------- launch 7: mean-pool + output head (warp per graph) --------
__global__ void k_pool(const float* __restrict__ h, const int* __restrict__ batch,
                       const float* __restrict__ Wout, const float* __restrict__ bout,
                       float* __restrict__ out) {
    int g = (blockIdx.x * blockDim.x + threadIdx.x) >> 5;
    if (g >= N_GRAPHS) return;
    int lane = threadIdx.x & 31;
    int s, e;
    { int lo = 0, hi = N_NODES;
      while (lo < hi) { int m = (lo + hi) >> 1; if (__ldg(batch + m) < g) lo = m + 1; else hi = m; }
      s = lo; }
    { int lo = s, hi = N_NODES;
      while (lo < hi) { int m = (lo + hi) >> 1; if (__ldg(batch + m) < g + 1) lo = m + 1; else hi = m; }
      e = lo; }
    float a0 = 0.f, a1 = 0.f;
    for (int n = s; n < e; ++n) {
        a0 += h[n * 64 + lane];
        a1 += h[n * 64 + lane + 32];
    }
    float inv = 1.f / (float)max(e - s, 1);
    a0 *= inv; a1 *= inv;
    float p0 = a0 * __ldg(Wout + lane * 2 + 0) + a1 * __ldg(Wout + (lane + 32) * 2 + 0);
    float p1 = a0 * __ldg(Wout + lane * 2 + 1) + a1 * __ldg(Wout + (lane + 32) * 2 + 1);
#pragma unroll
    for (int off = 16; off; off >>= 1) {
        p0 += __shfl_xor_sync(0xffffffffu, p0, off);
        p1 += __shfl_xor_sync(0xffffffffu, p1, off);
    }
    if (lane == 0) {
        out[g * 2 + 0] = p0 + __ldg(bout + 0);
        out[g * 2 + 1] = p1 + __ldg(bout + 1);
    }
}

// ---------------- launch ----------------
extern "C" void kernel_launch(void* const* d_in, const int* in_sizes, int n_in,
                              void* d_out, int out_size) {
    const int*   x     = (const int*)d_in[0];
    const int*   ei    = (const int*)d_in[1];
    const int*   batch = (const int*)d_in[2];
    const float* emb   = (const float*)d_in[3];
    const float* W1l   = (const float*)d_in[4];
    const float* b1    = (const float*)d_in[5];
    const float* W1r   = (const float*)d_in[6];
    const float* W2l   = (const float*)d_in[7];
    const float* b2    = (const float*)d_in[8];
    const float* W2r   = (const float*)d_in[9];
    const float* Wo    = (const float*)d_in[10];
    const float* bo    = (const float*)d_in[11];
    const int* src = ei;
    const int* dst = ei + N_EDGES;
    float* out = (float*)d_out;

    float *hA, *hB, *mean;
    cudaGetSymbolAddress((void**)&hA, g_hA);
    cudaGetSymbolAddress((void**)&hB, g_hB);
    cudaGetSymbolAddress((void**)&mean, g_mean);

    // 1: weight transform + dst histogram + lb reset
    k_prep<<<128 + ((N_EDGES + 511) / 512), 256>>>(emb, W1l, W1r, dst);
    // 2: rowptr/cursor via lookback scan
    k_scanlb<<<SCAN_NB, SCAN_BS>>>();
    // 3: CSR fill, packed node|vid (+ restore deg==0)
    k_fill<<<(N_EDGES + 255) / 256, 256>>>(src, dst, x);

    // 4: conv1 fully fused (L1-resident E' gather)   <-- ncu capture slot
    k_agg1<<<(N_NODES * 32 + 255) / 256, 256>>>(x, b1, hB);

    // 5-6: conv2
    k_agg<<<(N_NODES * 32 + 255) / 256, 256>>>(hB, mean);
    k_mm<<<(N_NODES + 255) / 256, 256>>>(mean, hB, W2l, W2r, b2, hA);

    // 7: pool + head
    k_pool<<<(N_GRAPHS * 32 + 255) / 256, 256>>>(hA, batch, Wo, bo, out);
}